// round 1
// baseline (speedup 1.0000x reference)
#include <cuda_runtime.h>
#include <cstdint>

#define N_NODES 200000
#define DIM     64
#define NNZ_E   6400000
#define NE      (N_NODES * DIM)          // 12,800,000 floats per dense matrix

// Scratch (allocation-free rule: __device__ globals). 3 x 51.2 MB.
__device__ float g_bufA[NE];
__device__ float g_bufB[NE];
__device__ float g_bufS[NE];

// ---------------------------------------------------------------------------
// logmap0 on the hyperboloid (c=1): h[:,0]=0, h[:,1:] = acosh(x0) * y / ||y||
// One warp per row; lane l handles columns {2l, 2l+1} as a float2.
// ---------------------------------------------------------------------------
__global__ void logmap_kernel(const float* __restrict__ x, float* __restrict__ h) {
    int row  = blockIdx.x * (blockDim.x >> 5) + (threadIdx.x >> 5);
    int lane = threadIdx.x & 31;
    if (row >= N_NODES) return;

    const float2* xr = reinterpret_cast<const float2*>(x + (size_t)row * DIM);
    float2 v = xr[lane];

    float x0 = __shfl_sync(0xFFFFFFFFu, v.x, 0);
    // y = x[1:64]; lane 0's v.x is x0 (excluded from the norm)
    float ss = v.y * v.y + (lane ? v.x * v.x : 0.0f);
    #pragma unroll
    for (int o = 16; o; o >>= 1) ss += __shfl_xor_sync(0xFFFFFFFFu, ss, o);

    float y_norm = fmaxf(sqrtf(ss), 1e-15f);
    float theta  = fmaxf(x0, 1.0f + 1e-7f);
    float s      = acoshf(theta) / y_norm;

    float2 o2;
    o2.x = lane ? s * v.x : 0.0f;   // column 0 -> 0
    o2.y = s * v.y;
    reinterpret_cast<float2*>(h + (size_t)row * DIM)[lane] = o2;
}

// ---------------------------------------------------------------------------
// Streaming elementwise kernels (float4, grid-stride)
// ---------------------------------------------------------------------------
__global__ void zero_kernel(float4* __restrict__ p, int n4) {
    int i = blockIdx.x * blockDim.x + threadIdx.x;
    float4 z = {0.f, 0.f, 0.f, 0.f};
    for (; i < n4; i += gridDim.x * blockDim.x) p[i] = z;
}

// d1 = d2 = src  (S = cur; next-layer accumulator init = S)
__global__ void copy2_kernel(const float4* __restrict__ src,
                             float4* __restrict__ d1, float4* __restrict__ d2, int n4) {
    int i = blockIdx.x * blockDim.x + threadIdx.x;
    for (; i < n4; i += gridDim.x * blockDim.x) {
        float4 v = src[i];
        d1[i] = v;
        d2[i] = v;
    }
}

// S += cur; next = S   (fused prefix update + next-layer accumulator init)
__global__ void addcopy_kernel(float4* __restrict__ S, const float4* __restrict__ cur,
                               float4* __restrict__ next, int n4) {
    int i = blockIdx.x * blockDim.x + threadIdx.x;
    for (; i < n4; i += gridDim.x * blockDim.x) {
        float4 s = S[i], c = cur[i];
        s.x += c.x; s.y += c.y; s.z += c.z; s.w += c.w;
        S[i]    = s;
        next[i] = s;
    }
}

// ---------------------------------------------------------------------------
// COO SpMM accumulate: out[rows[e]] += vals[e] * prev[cols[e]]  (D=64)
// 16 threads per edge, each thread moves one float4 (16 B).
// Scatter via red.global.add.v4.f32 (no return, 16 B per L2 reduction op).
// ---------------------------------------------------------------------------
__global__ void __launch_bounds__(256)
spmm_kernel(const int* __restrict__ rows, const int* __restrict__ cols,
            const float* __restrict__ vals, const float* __restrict__ prev,
            float* __restrict__ out) {
    long long t = (long long)blockIdx.x * blockDim.x + threadIdx.x;
    int e    = (int)(t >> 4);
    int lane = (int)(t & 15);
    if (e >= NNZ_E) return;

    int   r = __ldg(rows + e);
    int   c = __ldg(cols + e);
    float v = __ldg(vals + e);

    float4 p = __ldg(reinterpret_cast<const float4*>(prev + (size_t)c * DIM) + lane);
    float4 q;
    q.x = v * p.x; q.y = v * p.y; q.z = v * p.z; q.w = v * p.w;

    float* dst = out + (size_t)r * DIM + lane * 4;
    asm volatile("red.global.add.v4.f32 [%0], {%1, %2, %3, %4};"
                 :: "l"(dst), "f"(q.x), "f"(q.y), "f"(q.z), "f"(q.w)
                 : "memory");
}

// ---------------------------------------------------------------------------
// Launch sequence:
//   h = logmap0(x)               -> bufA ; bufB = 0
//   cur0 = spmm(h)               -> bufB ; S = cur0 ; bufA = S
//   cur1 = S + spmm(cur0)        -> bufA ; S += cur1 ; bufB = S
//   cur2 = S + spmm(cur1)        -> bufB ; S += cur2 ; d_out = S
//   cur3 = S + spmm(cur2)        -> d_out   (== final result)
// ---------------------------------------------------------------------------
extern "C" void kernel_launch(void* const* d_in, const int* in_sizes, int n_in,
                              void* d_out, int out_size) {
    const float* x    = (const float*)d_in[0];
    const int*   rows = (const int*)  d_in[1];
    const int*   cols = (const int*)  d_in[2];
    const float* vals = (const float*)d_in[3];
    float*       out  = (float*)d_out;

    float *bufA, *bufB, *bufS;
    cudaGetSymbolAddress((void**)&bufA, g_bufA);
    cudaGetSymbolAddress((void**)&bufB, g_bufB);
    cudaGetSymbolAddress((void**)&bufS, g_bufS);

    const int n4 = NE / 4;                      // 3.2M float4
    const int EW_BLOCKS = 1184;                 // 8 blocks/SM on 148 SMs
    const int EW_THREADS = 256;

    // logmap: 8 rows per 256-thread block
    {
        int rows_per_block = 256 / 32;
        int nb = (N_NODES + rows_per_block - 1) / rows_per_block;
        logmap_kernel<<<nb, 256>>>(x, bufA);
    }
    zero_kernel<<<EW_BLOCKS, EW_THREADS>>>((float4*)bufB, n4);

    const long long spmm_threads = (long long)NNZ_E * 16;
    const int spmm_blocks = (int)((spmm_threads + 255) / 256);

    // Layer 0
    spmm_kernel<<<spmm_blocks, 256>>>(rows, cols, vals, bufA, bufB);
    copy2_kernel<<<EW_BLOCKS, EW_THREADS>>>((const float4*)bufB, (float4*)bufS, (float4*)bufA, n4);
    // Layer 1
    spmm_kernel<<<spmm_blocks, 256>>>(rows, cols, vals, bufB, bufA);
    addcopy_kernel<<<EW_BLOCKS, EW_THREADS>>>((float4*)bufS, (const float4*)bufA, (float4*)bufB, n4);
    // Layer 2
    spmm_kernel<<<spmm_blocks, 256>>>(rows, cols, vals, bufA, bufB);
    addcopy_kernel<<<EW_BLOCKS, EW_THREADS>>>((float4*)bufS, (const float4*)bufB, (float4*)out, n4);
    // Layer 3 (accumulates directly into d_out, which was pre-set to S)
    spmm_kernel<<<spmm_blocks, 256>>>(rows, cols, vals, bufB, out);
}

// round 2
// speedup vs baseline: 2.0655x; 2.0655x over previous
#include <cuda_runtime.h>
#include <cstdint>

#define N_NODES 200000
#define DIM     64
#define NNZ_E   6400000
#define NE      (N_NODES * DIM)

// Scratch: __device__ globals (allocation-free rule). ~205 MB total.
__device__ float g_bufA[NE];            // 51.2 MB
__device__ float g_bufB[NE];            // 51.2 MB
__device__ float g_bufS[NE];            // 51.2 MB
__device__ int2  g_cv[NNZ_E];           // 51.2 MB  (col, val-bits) row-sorted
__device__ int   g_cnt[N_NODES];
__device__ int   g_rowptr[N_NODES + 1];
__device__ int   g_off[N_NODES];

// ---------------------------------------------------------------------------
// logmap0 hyperboloid (c=1): h[:,0]=0, h[:,1:] = acosh(x0) * y / ||y||
// one warp per row; lane handles a float2
// ---------------------------------------------------------------------------
__global__ void logmap_kernel(const float* __restrict__ x, float* __restrict__ h) {
    int row  = blockIdx.x * (blockDim.x >> 5) + (threadIdx.x >> 5);
    int lane = threadIdx.x & 31;
    if (row >= N_NODES) return;

    float2 v = reinterpret_cast<const float2*>(x + (size_t)row * DIM)[lane];
    float x0 = __shfl_sync(0xFFFFFFFFu, v.x, 0);
    float ss = v.y * v.y + (lane ? v.x * v.x : 0.0f);
    #pragma unroll
    for (int o = 16; o; o >>= 1) ss += __shfl_xor_sync(0xFFFFFFFFu, ss, o);

    float y_norm = fmaxf(sqrtf(ss), 1e-15f);
    float theta  = fmaxf(x0, 1.0f + 1e-7f);
    float s      = acoshf(theta) / y_norm;

    float2 o2;
    o2.x = lane ? s * v.x : 0.0f;
    o2.y = s * v.y;
    reinterpret_cast<float2*>(h + (size_t)row * DIM)[lane] = o2;
}

// ---------------------------------------------------------------------------
// CSR construction (runs every launch, graph-capturable, amortized over 4 layers)
// ---------------------------------------------------------------------------
__global__ void zero_cnt_kernel(int* __restrict__ cnt) {
    int i = blockIdx.x * blockDim.x + threadIdx.x;
    for (; i < N_NODES; i += gridDim.x * blockDim.x) cnt[i] = 0;
}

__global__ void hist_kernel(const int* __restrict__ rows, int* __restrict__ cnt) {
    int i = blockIdx.x * blockDim.x + threadIdx.x;
    for (; i < NNZ_E; i += gridDim.x * blockDim.x)
        atomicAdd(&cnt[rows[i]], 1);
}

// single-block chunked exclusive scan: cnt -> rowptr (and a scatter cursor copy)
__global__ void scan_kernel(const int* __restrict__ cnt,
                            int* __restrict__ rowptr, int* __restrict__ off) {
    __shared__ int ws[32];
    __shared__ int carry_s;
    int tid = threadIdx.x, lane = tid & 31, wid = tid >> 5;
    if (tid == 0) carry_s = 0;
    __syncthreads();

    for (int base = 0; base < N_NODES; base += 1024) {
        int i = base + tid;
        int v = (i < N_NODES) ? cnt[i] : 0;
        int x = v;
        #pragma unroll
        for (int o = 1; o < 32; o <<= 1) {
            int y = __shfl_up_sync(0xFFFFFFFFu, x, o);
            if (lane >= o) x += y;
        }
        if (lane == 31) ws[wid] = x;
        __syncthreads();
        if (wid == 0) {
            int s = ws[lane];
            #pragma unroll
            for (int o = 1; o < 32; o <<= 1) {
                int y = __shfl_up_sync(0xFFFFFFFFu, s, o);
                if (lane >= o) s += y;
            }
            ws[lane] = s;
        }
        __syncthreads();
        int carry     = carry_s;
        int warp_excl = wid ? ws[wid - 1] : 0;
        int excl      = carry + warp_excl + (x - v);
        if (i < N_NODES) { rowptr[i] = excl; off[i] = excl; }
        __syncthreads();
        if (tid == 0) carry_s = carry + ws[31];
        __syncthreads();
    }
    if (tid == 0) rowptr[N_NODES] = carry_s;   // == NNZ_E
}

__global__ void scatter_kernel(const int* __restrict__ rows, const int* __restrict__ cols,
                               const float* __restrict__ vals,
                               int* __restrict__ off, int2* __restrict__ cv) {
    int i = blockIdx.x * blockDim.x + threadIdx.x;
    for (; i < NNZ_E; i += gridDim.x * blockDim.x) {
        int r   = rows[i];
        int pos = atomicAdd(&off[r], 1);
        cv[pos] = make_int2(cols[i], __float_as_int(vals[i]));
    }
}

// ---------------------------------------------------------------------------
// Fused CSR SpMM layer:
//   acc = sum_e val*prev[col]        (register accumulation, no atomics)
//   first: cur = acc;       S = acc
//   mid:   cur = S + acc;   S = S + cur
//   last:  cur = S + acc    (no S write; cur -> d_out)
// one warp per row, lane owns a float2 of the 64-dim feature
// ---------------------------------------------------------------------------
__global__ void __launch_bounds__(256)
csr_layer_kernel(const int* __restrict__ rowptr, const int2* __restrict__ cv,
                 const float* __restrict__ prev, float* __restrict__ cur,
                 float* __restrict__ S, int first, int last) {
    int row  = blockIdx.x * 8 + (threadIdx.x >> 5);
    int lane = threadIdx.x & 31;
    if (row >= N_NODES) return;

    int beg = __ldg(rowptr + row);
    int end = __ldg(rowptr + row + 1);

    const float2* pv = reinterpret_cast<const float2*>(prev);
    float ax = 0.0f, ay = 0.0f;

    int e = beg;
    for (; e + 4 <= end; e += 4) {
        int2 c0 = __ldg(cv + e);
        int2 c1 = __ldg(cv + e + 1);
        int2 c2 = __ldg(cv + e + 2);
        int2 c3 = __ldg(cv + e + 3);
        float2 p0 = __ldg(pv + (size_t)c0.x * 32 + lane);
        float2 p1 = __ldg(pv + (size_t)c1.x * 32 + lane);
        float2 p2 = __ldg(pv + (size_t)c2.x * 32 + lane);
        float2 p3 = __ldg(pv + (size_t)c3.x * 32 + lane);
        float v0 = __int_as_float(c0.y), v1 = __int_as_float(c1.y);
        float v2 = __int_as_float(c2.y), v3 = __int_as_float(c3.y);
        ax = fmaf(v0, p0.x, ax); ay = fmaf(v0, p0.y, ay);
        ax = fmaf(v1, p1.x, ax); ay = fmaf(v1, p1.y, ay);
        ax = fmaf(v2, p2.x, ax); ay = fmaf(v2, p2.y, ay);
        ax = fmaf(v3, p3.x, ax); ay = fmaf(v3, p3.y, ay);
    }
    for (; e < end; ++e) {
        int2 c = __ldg(cv + e);
        float2 p = __ldg(pv + (size_t)c.x * 32 + lane);
        float v = __int_as_float(c.y);
        ax = fmaf(v, p.x, ax); ay = fmaf(v, p.y, ay);
    }

    size_t o = (size_t)row * 32 + lane;
    float2 outv, snew;
    if (first) {
        outv = make_float2(ax, ay);
        snew = outv;
    } else {
        float2 s = __ldg(reinterpret_cast<const float2*>(S) + o);
        outv = make_float2(s.x + ax, s.y + ay);
        snew = make_float2(s.x + outv.x, s.y + outv.y);
    }
    reinterpret_cast<float2*>(cur)[o] = outv;
    if (!last) reinterpret_cast<float2*>(S)[o] = snew;
}

// ---------------------------------------------------------------------------
extern "C" void kernel_launch(void* const* d_in, const int* in_sizes, int n_in,
                              void* d_out, int out_size) {
    const float* x    = (const float*)d_in[0];
    const int*   rows = (const int*)  d_in[1];
    const int*   cols = (const int*)  d_in[2];
    const float* vals = (const float*)d_in[3];
    float*       out  = (float*)d_out;

    float *bufA, *bufB, *bufS;
    int2  *cv;
    int   *cnt, *rowptr, *off;
    cudaGetSymbolAddress((void**)&bufA,   g_bufA);
    cudaGetSymbolAddress((void**)&bufB,   g_bufB);
    cudaGetSymbolAddress((void**)&bufS,   g_bufS);
    cudaGetSymbolAddress((void**)&cv,     g_cv);
    cudaGetSymbolAddress((void**)&cnt,    g_cnt);
    cudaGetSymbolAddress((void**)&rowptr, g_rowptr);
    cudaGetSymbolAddress((void**)&off,    g_off);

    const int EDGE_BLOCKS = (NNZ_E + 255) / 256;     // 25000
    const int ROW_BLOCKS  = (N_NODES + 7) / 8;       // 25000 (8 warps/block)

    // CSR build (amortized over 4 layers)
    zero_cnt_kernel<<<256, 256>>>(cnt);
    hist_kernel<<<4096, 256>>>(rows, cnt);
    scan_kernel<<<1, 1024>>>(cnt, rowptr, off);
    scatter_kernel<<<4096, 256>>>(rows, cols, vals, off, cv);

    // h = logmap0(x) -> bufA
    logmap_kernel<<<(N_NODES + 7) / 8, 256>>>(x, bufA);

    // 4 fused layers (no atomics, no separate elementwise passes)
    csr_layer_kernel<<<ROW_BLOCKS, 256>>>(rowptr, cv, bufA, bufB, bufS, 1, 0);
    csr_layer_kernel<<<ROW_BLOCKS, 256>>>(rowptr, cv, bufB, bufA, bufS, 0, 0);
    csr_layer_kernel<<<ROW_BLOCKS, 256>>>(rowptr, cv, bufA, bufB, bufS, 0, 0);
    csr_layer_kernel<<<ROW_BLOCKS, 256>>>(rowptr, cv, bufB, out,  bufS, 0, 1);
}

// round 3
// speedup vs baseline: 2.6151x; 1.2661x over previous
#include <cuda_runtime.h>
#include <cuda_fp16.h>
#include <cstdint>

#define N_NODES 200000
#define DIM     64
#define NNZ_E   6400000
#define NE      (N_NODES * DIM)
#define SCAN_CHUNK 2048
#define SCAN_NBLK  ((N_NODES + SCAN_CHUNK - 1) / SCAN_CHUNK)   // 98

// Scratch: __device__ globals (allocation-free rule).
__device__ __half g_h16A[NE];           // 25.6 MB (layer input, fp16)
__device__ __half g_h16B[NE];           // 25.6 MB (layer output, fp16)
__device__ float  g_bufS[NE];           // 51.2 MB (prefix S, fp32)
__device__ int2   g_cv[NNZ_E];          // 51.2 MB (col, val-bits) row-grouped
__device__ int    g_cnt[N_NODES];
__device__ int    g_rowptr[N_NODES + 1];
__device__ int    g_off[N_NODES];
__device__ int    g_blksum[SCAN_NBLK];
__device__ int    g_blkoff[SCAN_NBLK];

// ---------------------------------------------------------------------------
// logmap0 hyperboloid (c=1): h[:,0]=0, h[:,1:] = acosh(x0)*y/||y||  -> fp16
// ---------------------------------------------------------------------------
__global__ void logmap_kernel(const float* __restrict__ x, __half2* __restrict__ h) {
    int row  = blockIdx.x * (blockDim.x >> 5) + (threadIdx.x >> 5);
    int lane = threadIdx.x & 31;
    if (row >= N_NODES) return;

    float2 v = reinterpret_cast<const float2*>(x + (size_t)row * DIM)[lane];
    float x0 = __shfl_sync(0xFFFFFFFFu, v.x, 0);
    float ss = v.y * v.y + (lane ? v.x * v.x : 0.0f);
    #pragma unroll
    for (int o = 16; o; o >>= 1) ss += __shfl_xor_sync(0xFFFFFFFFu, ss, o);

    float y_norm = fmaxf(sqrtf(ss), 1e-15f);
    float theta  = fmaxf(x0, 1.0f + 1e-7f);
    float s      = acoshf(theta) / y_norm;

    float2 o2;
    o2.x = lane ? s * v.x : 0.0f;
    o2.y = s * v.y;
    h[(size_t)row * 32 + lane] = __float22half2_rn(o2);
}

// ---------------------------------------------------------------------------
// CSR build: hist -> multi-block scan (3 kernels) -> scatter
// ---------------------------------------------------------------------------
__global__ void hist_kernel(const int* __restrict__ rows, int* __restrict__ cnt) {
    int i = blockIdx.x * blockDim.x + threadIdx.x;
    for (; i < NNZ_E; i += gridDim.x * blockDim.x)
        atomicAdd(&cnt[rows[i]], 1);
}

// per-block exclusive scan of a 2048 chunk; block total -> blksum
__global__ void scan1_kernel(const int* __restrict__ cnt,
                             int* __restrict__ rowptr, int* __restrict__ blksum) {
    __shared__ int ws[32];
    __shared__ int carry_s;
    int tid = threadIdx.x, lane = tid & 31, wid = tid >> 5;
    int base0 = blockIdx.x * SCAN_CHUNK;
    if (tid == 0) carry_s = 0;
    __syncthreads();

    #pragma unroll
    for (int it = 0; it < SCAN_CHUNK / 1024; ++it) {
        int i = base0 + it * 1024 + tid;
        int v = (i < N_NODES) ? cnt[i] : 0;
        int x = v;
        #pragma unroll
        for (int o = 1; o < 32; o <<= 1) {
            int y = __shfl_up_sync(0xFFFFFFFFu, x, o);
            if (lane >= o) x += y;
        }
        if (lane == 31) ws[wid] = x;
        __syncthreads();
        if (wid == 0) {
            int s = ws[lane];
            #pragma unroll
            for (int o = 1; o < 32; o <<= 1) {
                int y = __shfl_up_sync(0xFFFFFFFFu, s, o);
                if (lane >= o) s += y;
            }
            ws[lane] = s;
        }
        __syncthreads();
        int carry = carry_s;
        int excl  = carry + (wid ? ws[wid - 1] : 0) + (x - v);
        if (i < N_NODES) rowptr[i] = excl;
        __syncthreads();
        if (tid == 0) carry_s = carry + ws[31];
        __syncthreads();
    }
    if (tid == 0) blksum[blockIdx.x] = carry_s;
}

// single warp scans the 98 block sums
__global__ void scan2_kernel(const int* __restrict__ blksum, int* __restrict__ blkoff) {
    int lane = threadIdx.x;
    int carry = 0;
    for (int base = 0; base < SCAN_NBLK; base += 32) {
        int i = base + lane;
        int v = (i < SCAN_NBLK) ? blksum[i] : 0;
        int x = v;
        #pragma unroll
        for (int o = 1; o < 32; o <<= 1) {
            int y = __shfl_up_sync(0xFFFFFFFFu, x, o);
            if (lane >= o) x += y;
        }
        if (i < SCAN_NBLK) blkoff[i] = carry + x - v;
        carry += __shfl_sync(0xFFFFFFFFu, x, 31);
    }
}

// add block offsets; copy cursor; set sentinel
__global__ void scan3_kernel(int* __restrict__ rowptr, const int* __restrict__ blkoff,
                             int* __restrict__ off) {
    int i = blockIdx.x * blockDim.x + threadIdx.x;
    for (; i < N_NODES; i += gridDim.x * blockDim.x) {
        int v = rowptr[i] + blkoff[i / SCAN_CHUNK];
        rowptr[i] = v;
        off[i]    = v;
    }
    if (blockIdx.x == 0 && threadIdx.x == 0) rowptr[N_NODES] = NNZ_E;
}

__global__ void scatter_kernel(const int* __restrict__ rows, const int* __restrict__ cols,
                               const float* __restrict__ vals,
                               int* __restrict__ off, int2* __restrict__ cv) {
    int i = blockIdx.x * blockDim.x + threadIdx.x;
    for (; i < NNZ_E; i += gridDim.x * blockDim.x) {
        int r   = rows[i];
        int pos = atomicAdd(&off[r], 1);
        cv[pos] = make_int2(cols[i], __float_as_int(vals[i]));
    }
}

// ---------------------------------------------------------------------------
// Fused CSR SpMM layer (fp16 gather, fp32 accumulate):
//   acc = sum_e val * prev16[col]
//   first: cur = acc;     S = acc
//   mid:   cur = S + acc; S += cur
//   last:  out = S + acc  (fp32, no cur16/S writes)
// one warp per row, lane owns dims {2l, 2l+1}
// ---------------------------------------------------------------------------
__global__ void __launch_bounds__(256)
csr_layer_kernel(const int* __restrict__ rowptr, const int2* __restrict__ cv,
                 const __half2* __restrict__ prev, __half2* __restrict__ cur,
                 float* __restrict__ S, float* __restrict__ out,
                 int first, int last) {
    int row  = blockIdx.x * 8 + (threadIdx.x >> 5);
    int lane = threadIdx.x & 31;
    if (row >= N_NODES) return;

    int beg = __ldg(rowptr + row);
    int end = __ldg(rowptr + row + 1);

    float ax = 0.0f, ay = 0.0f;

    int e = beg;
    for (; e + 4 <= end; e += 4) {
        int2 c0 = __ldg(cv + e);
        int2 c1 = __ldg(cv + e + 1);
        int2 c2 = __ldg(cv + e + 2);
        int2 c3 = __ldg(cv + e + 3);
        __half2 h0 = __ldg(prev + (size_t)c0.x * 32 + lane);
        __half2 h1 = __ldg(prev + (size_t)c1.x * 32 + lane);
        __half2 h2 = __ldg(prev + (size_t)c2.x * 32 + lane);
        __half2 h3 = __ldg(prev + (size_t)c3.x * 32 + lane);
        float2 p0 = __half22float2(h0);
        float2 p1 = __half22float2(h1);
        float2 p2 = __half22float2(h2);
        float2 p3 = __half22float2(h3);
        float v0 = __int_as_float(c0.y), v1 = __int_as_float(c1.y);
        float v2 = __int_as_float(c2.y), v3 = __int_as_float(c3.y);
        ax = fmaf(v0, p0.x, ax); ay = fmaf(v0, p0.y, ay);
        ax = fmaf(v1, p1.x, ax); ay = fmaf(v1, p1.y, ay);
        ax = fmaf(v2, p2.x, ax); ay = fmaf(v2, p2.y, ay);
        ax = fmaf(v3, p3.x, ax); ay = fmaf(v3, p3.y, ay);
    }
    for (; e < end; ++e) {
        int2 c = __ldg(cv + e);
        float2 p = __half22float2(__ldg(prev + (size_t)c.x * 32 + lane));
        float v = __int_as_float(c.y);
        ax = fmaf(v, p.x, ax); ay = fmaf(v, p.y, ay);
    }

    size_t o = (size_t)row * 32 + lane;
    if (first) {
        cur[o] = __float22half2_rn(make_float2(ax, ay));
        reinterpret_cast<float2*>(S)[o] = make_float2(ax, ay);
    } else if (last) {
        float2 s = __ldg(reinterpret_cast<const float2*>(S) + o);
        reinterpret_cast<float2*>(out)[o] = make_float2(s.x + ax, s.y + ay);
    } else {
        float2 s = __ldg(reinterpret_cast<const float2*>(S) + o);
        float2 c = make_float2(s.x + ax, s.y + ay);
        cur[o] = __float22half2_rn(c);
        reinterpret_cast<float2*>(S)[o] = make_float2(s.x + c.x, s.y + c.y);
    }
}

// ---------------------------------------------------------------------------
extern "C" void kernel_launch(void* const* d_in, const int* in_sizes, int n_in,
                              void* d_out, int out_size) {
    const float* x    = (const float*)d_in[0];
    const int*   rows = (const int*)  d_in[1];
    const int*   cols = (const int*)  d_in[2];
    const float* vals = (const float*)d_in[3];
    float*       out  = (float*)d_out;

    __half *h16A, *h16B;
    float  *bufS;
    int2   *cv;
    int    *cnt, *rowptr, *off, *blksum, *blkoff;
    cudaGetSymbolAddress((void**)&h16A,   g_h16A);
    cudaGetSymbolAddress((void**)&h16B,   g_h16B);
    cudaGetSymbolAddress((void**)&bufS,   g_bufS);
    cudaGetSymbolAddress((void**)&cv,     g_cv);
    cudaGetSymbolAddress((void**)&cnt,    g_cnt);
    cudaGetSymbolAddress((void**)&rowptr, g_rowptr);
    cudaGetSymbolAddress((void**)&off,    g_off);
    cudaGetSymbolAddress((void**)&blksum, g_blksum);
    cudaGetSymbolAddress((void**)&blkoff, g_blkoff);

    const int ROW_BLOCKS = (N_NODES + 7) / 8;   // 25000 (8 warps/block)

    // CSR build (amortized over 4 layers)
    cudaMemsetAsync(cnt, 0, N_NODES * sizeof(int));
    hist_kernel<<<4096, 256>>>(rows, cnt);
    scan1_kernel<<<SCAN_NBLK, 1024>>>(cnt, rowptr, blksum);
    scan2_kernel<<<1, 32>>>(blksum, blkoff);
    scan3_kernel<<<256, 256>>>(rowptr, blkoff, off);
    scatter_kernel<<<4096, 256>>>(rows, cols, vals, off, cv);

    // h = logmap0(x) -> fp16 bufA
    logmap_kernel<<<(N_NODES + 7) / 8, 256>>>(x, (__half2*)h16A);

    // 4 fused layers
    csr_layer_kernel<<<ROW_BLOCKS, 256>>>(rowptr, cv, (__half2*)h16A, (__half2*)h16B, bufS, out, 1, 0);
    csr_layer_kernel<<<ROW_BLOCKS, 256>>>(rowptr, cv, (__half2*)h16B, (__half2*)h16A, bufS, out, 0, 0);
    csr_layer_kernel<<<ROW_BLOCKS, 256>>>(rowptr, cv, (__half2*)h16A, (__half2*)h16B, bufS, out, 0, 0);
    csr_layer_kernel<<<ROW_BLOCKS, 256>>>(rowptr, cv, (__half2*)h16B, (__half2*)h16A, bufS, out, 0, 1);
}

// round 4
// speedup vs baseline: 3.0005x; 1.1474x over previous
#include <cuda_runtime.h>
#include <cuda_fp16.h>
#include <cstdint>

#define N_NODES 200000
#define DIM     64
#define NNZ_E   6400000
#define NE      (N_NODES * DIM)
#define SCAN_CHUNK 2048
#define SCAN_NBLK  ((N_NODES + SCAN_CHUNK - 1) / SCAN_CHUNK)   // 98

// Scratch: __device__ globals (allocation-free rule). ~154 MB.
__device__ __half g_h[NE];              // 25.6 MB  h = logmap0(x)
__device__ __half g_m1[NE];             // 25.6 MB  m1 = A h
__device__ __half g_m2[NE];             // 25.6 MB  m2 = A m1
__device__ __half g_m3[NE];             // 25.6 MB  m3 = A m2
__device__ int2   g_cv[NNZ_E];          // 51.2 MB  (col, val-bits) row-grouped
__device__ int    g_cnt[N_NODES];
__device__ int    g_rowptr[N_NODES + 1];
__device__ int    g_off[N_NODES];
__device__ int    g_blksum[SCAN_NBLK];

// ---------------------------------------------------------------------------
// Launch 0: logmap0 (c=1) -> fp16 h ; also zeroes the histogram counters.
// one warp per row; lane owns dims {2l, 2l+1}
// ---------------------------------------------------------------------------
__global__ void logmap_kernel(const float* __restrict__ x, __half2* __restrict__ h,
                              int* __restrict__ cnt) {
    int gi = blockIdx.x * blockDim.x + threadIdx.x;
    if (gi < N_NODES) cnt[gi] = 0;            // grid has 6.4M threads >= N_NODES

    int row  = blockIdx.x * (blockDim.x >> 5) + (threadIdx.x >> 5);
    int lane = threadIdx.x & 31;
    if (row >= N_NODES) return;

    float2 v = reinterpret_cast<const float2*>(x + (size_t)row * DIM)[lane];
    float x0 = __shfl_sync(0xFFFFFFFFu, v.x, 0);
    float ss = v.y * v.y + (lane ? v.x * v.x : 0.0f);
    #pragma unroll
    for (int o = 16; o; o >>= 1) ss += __shfl_xor_sync(0xFFFFFFFFu, ss, o);

    float y_norm = fmaxf(sqrtf(ss), 1e-15f);
    float theta  = fmaxf(x0, 1.0f + 1e-7f);
    float s      = acoshf(theta) / y_norm;

    float2 o2;
    o2.x = lane ? s * v.x : 0.0f;
    o2.y = s * v.y;
    h[(size_t)row * 32 + lane] = __float22half2_rn(o2);
}

// ---------------------------------------------------------------------------
// Launch 1: histogram of row indices (int4-vectorized reads)
// ---------------------------------------------------------------------------
__global__ void hist_kernel(const int4* __restrict__ rows4, int* __restrict__ cnt) {
    int i = blockIdx.x * blockDim.x + threadIdx.x;
    for (; i < NNZ_E / 4; i += gridDim.x * blockDim.x) {
        int4 r = __ldg(rows4 + i);
        atomicAdd(&cnt[r.x], 1);
        atomicAdd(&cnt[r.y], 1);
        atomicAdd(&cnt[r.z], 1);
        atomicAdd(&cnt[r.w], 1);
    }
}

// ---------------------------------------------------------------------------
// Launch 2: per-block exclusive scan of 2048-chunks; chunk totals -> blksum
// ---------------------------------------------------------------------------
__global__ void scan1_kernel(const int* __restrict__ cnt,
                             int* __restrict__ rowptr, int* __restrict__ blksum) {
    __shared__ int ws[32];
    __shared__ int carry_s;
    int tid = threadIdx.x, lane = tid & 31, wid = tid >> 5;
    int base0 = blockIdx.x * SCAN_CHUNK;
    if (tid == 0) carry_s = 0;
    __syncthreads();

    #pragma unroll
    for (int it = 0; it < SCAN_CHUNK / 1024; ++it) {
        int i = base0 + it * 1024 + tid;
        int v = (i < N_NODES) ? cnt[i] : 0;
        int x = v;
        #pragma unroll
        for (int o = 1; o < 32; o <<= 1) {
            int y = __shfl_up_sync(0xFFFFFFFFu, x, o);
            if (lane >= o) x += y;
        }
        if (lane == 31) ws[wid] = x;
        __syncthreads();
        if (wid == 0) {
            int s = ws[lane];
            #pragma unroll
            for (int o = 1; o < 32; o <<= 1) {
                int y = __shfl_up_sync(0xFFFFFFFFu, s, o);
                if (lane >= o) s += y;
            }
            ws[lane] = s;
        }
        __syncthreads();
        int carry = carry_s;
        int excl  = carry + (wid ? ws[wid - 1] : 0) + (x - v);
        if (i < N_NODES) rowptr[i] = excl;
        __syncthreads();
        if (tid == 0) carry_s = carry + ws[31];
        __syncthreads();
    }
    if (tid == 0) blksum[blockIdx.x] = carry_s;
}

// ---------------------------------------------------------------------------
// Launch 3: fused block-offset scan + apply. Every block re-scans the 98
// block sums in SMEM (cheap), then adds offsets over its stripe.
// ---------------------------------------------------------------------------
__global__ void scan3_kernel(int* __restrict__ rowptr, const int* __restrict__ blksum,
                             int* __restrict__ off) {
    __shared__ int boff[SCAN_NBLK];
    int tid = threadIdx.x, lane = tid & 31;
    if (tid < 32) {
        int carry = 0;
        for (int base = 0; base < SCAN_NBLK; base += 32) {
            int i = base + lane;
            int v = (i < SCAN_NBLK) ? blksum[i] : 0;
            int x = v;
            #pragma unroll
            for (int o = 1; o < 32; o <<= 1) {
                int y = __shfl_up_sync(0xFFFFFFFFu, x, o);
                if (lane >= o) x += y;
            }
            if (i < SCAN_NBLK) boff[i] = carry + x - v;
            carry += __shfl_sync(0xFFFFFFFFu, x, 31);
        }
    }
    __syncthreads();

    int i = blockIdx.x * blockDim.x + tid;
    for (; i < N_NODES; i += gridDim.x * blockDim.x) {
        int v = rowptr[i] + boff[i / SCAN_CHUNK];
        rowptr[i] = v;
        off[i]    = v;
    }
    if (blockIdx.x == 0 && tid == 0) rowptr[N_NODES] = NNZ_E;
}

// ---------------------------------------------------------------------------
// Launch 4: scatter (col,val) into row-grouped cv; 2 edges/thread
// ---------------------------------------------------------------------------
__global__ void scatter_kernel(const int2* __restrict__ rows2, const int2* __restrict__ cols2,
                               const float2* __restrict__ vals2,
                               int* __restrict__ off, int2* __restrict__ cv) {
    int i = blockIdx.x * blockDim.x + threadIdx.x;
    for (; i < NNZ_E / 2; i += gridDim.x * blockDim.x) {
        int2   r = __ldg(rows2 + i);
        int2   c = __ldg(cols2 + i);
        float2 v = __ldg(vals2 + i);
        int p0 = atomicAdd(&off[r.x], 1);
        cv[p0] = make_int2(c.x, __float_as_int(v.x));
        int p1 = atomicAdd(&off[r.y], 1);
        cv[p1] = make_int2(c.y, __float_as_int(v.y));
    }
}

// ---------------------------------------------------------------------------
// Launches 5-8: CSR SpMM  dst = A * src  (fp16 gather, fp32 accumulate)
// last layer fuses: out = 4*m1 + 5*m2 + 3*m3 + A*m3   (fp32 output)
// one warp per row; lane owns dims {2l, 2l+1}; unroll-8 gather for MLP
// ---------------------------------------------------------------------------
__global__ void __launch_bounds__(256)
csr_spmm_kernel(const int* __restrict__ rowptr, const int2* __restrict__ cv,
                const __half2* __restrict__ src, __half2* __restrict__ dst,
                const __half2* __restrict__ m1, const __half2* __restrict__ m2,
                const __half2* __restrict__ m3, float* __restrict__ out, int last) {
    int row  = blockIdx.x * 8 + (threadIdx.x >> 5);
    int lane = threadIdx.x & 31;
    if (row >= N_NODES) return;

    int beg = __ldg(rowptr + row);
    int end = __ldg(rowptr + row + 1);

    float ax = 0.0f, ay = 0.0f;
    int e = beg;

    for (; e + 8 <= end; e += 8) {
        int2 c[8];
        #pragma unroll
        for (int k = 0; k < 8; ++k) c[k] = __ldg(cv + e + k);
        __half2 hh[8];
        #pragma unroll
        for (int k = 0; k < 8; ++k)
            hh[k] = __ldg(src + (size_t)c[k].x * 32 + lane);
        #pragma unroll
        for (int k = 0; k < 8; ++k) {
            float2 p = __half22float2(hh[k]);
            float  v = __int_as_float(c[k].y);
            ax = fmaf(v, p.x, ax);
            ay = fmaf(v, p.y, ay);
        }
    }
    for (; e < end; ++e) {
        int2 c = __ldg(cv + e);
        float2 p = __half22float2(__ldg(src + (size_t)c.x * 32 + lane));
        float v = __int_as_float(c.y);
        ax = fmaf(v, p.x, ax);
        ay = fmaf(v, p.y, ay);
    }

    size_t o = (size_t)row * 32 + lane;
    if (!last) {
        dst[o] = __float22half2_rn(make_float2(ax, ay));
    } else {
        float2 r1 = __half22float2(__ldg(m1 + o));
        float2 r2 = __half22float2(__ldg(m2 + o));
        float2 r3 = __half22float2(__ldg(m3 + o));
        float2 ov;
        ov.x = fmaf(4.0f, r1.x, fmaf(5.0f, r2.x, fmaf(3.0f, r3.x, ax)));
        ov.y = fmaf(4.0f, r1.y, fmaf(5.0f, r2.y, fmaf(3.0f, r3.y, ay)));
        reinterpret_cast<float2*>(out)[o] = ov;
    }
}

// ---------------------------------------------------------------------------
extern "C" void kernel_launch(void* const* d_in, const int* in_sizes, int n_in,
                              void* d_out, int out_size) {
    const float* x    = (const float*)d_in[0];
    const int*   rows = (const int*)  d_in[1];
    const int*   cols = (const int*)  d_in[2];
    const float* vals = (const float*)d_in[3];
    float*       out  = (float*)d_out;

    __half *h, *m1, *m2, *m3;
    int2   *cv;
    int    *cnt, *rowptr, *off, *blksum;
    cudaGetSymbolAddress((void**)&h,      g_h);
    cudaGetSymbolAddress((void**)&m1,     g_m1);
    cudaGetSymbolAddress((void**)&m2,     g_m2);
    cudaGetSymbolAddress((void**)&m3,     g_m3);
    cudaGetSymbolAddress((void**)&cv,     g_cv);
    cudaGetSymbolAddress((void**)&cnt,    g_cnt);
    cudaGetSymbolAddress((void**)&rowptr, g_rowptr);
    cudaGetSymbolAddress((void**)&off,    g_off);
    cudaGetSymbolAddress((void**)&blksum, g_blksum);

    const int ROW_BLOCKS = (N_NODES + 7) / 8;   // 25000

    // 0: logmap + zero cnt
    logmap_kernel<<<ROW_BLOCKS, 256>>>(x, (__half2*)h, cnt);
    // 1-4: CSR build
    hist_kernel<<<4096, 256>>>((const int4*)rows, cnt);
    scan1_kernel<<<SCAN_NBLK, 1024>>>(cnt, rowptr, blksum);
    scan3_kernel<<<256, 256>>>(rowptr, blksum, off);
    scatter_kernel<<<8192, 256>>>((const int2*)rows, (const int2*)cols,
                                  (const float2*)vals, off, cv);
    // 5-8: power-basis layers, final combine fused into layer 4
    csr_spmm_kernel<<<ROW_BLOCKS, 256>>>(rowptr, cv, (__half2*)h,  (__half2*)m1,
                                         nullptr, nullptr, nullptr, nullptr, 0);
    csr_spmm_kernel<<<ROW_BLOCKS, 256>>>(rowptr, cv, (__half2*)m1, (__half2*)m2,
                                         nullptr, nullptr, nullptr, nullptr, 0);
    csr_spmm_kernel<<<ROW_BLOCKS, 256>>>(rowptr, cv, (__half2*)m2, (__half2*)m3,
                                         nullptr, nullptr, nullptr, nullptr, 0);
    csr_spmm_kernel<<<ROW_BLOCKS, 256>>>(rowptr, cv, (__half2*)m3, nullptr,
                                         (const __half2*)m1, (const __half2*)m2,
                                         (const __half2*)m3, out, 1);
}